// round 3
// baseline (speedup 1.0000x reference)
#include <cuda_runtime.h>

// DynamicFilterLayer: out[b,0,y,x] = sum_{ky,kx in 11x11} image[b,0,y+ky-5,x+kx-5] * filters[b,ky*11+kx,y,x]
// image:   (16, 1, 256, 256)  float32  (4 MB, reused 121x -> shared tile)
// filters: (16, 121, 256, 256) float32 (2.03 GB, read once -> __ldcs stream)
// out:     (16, 1, 256, 256)  float32
//
// Pure HBM-stream kernel: floor ~ 2.04 GB / ~6.5 TB/s ~ 320 us.

#define H 256
#define W 256
#define KH 11
#define KW 11
#define HALO 5
#define TAPS 121
#define TILE_X 128          // output pixels in x per block (32 threads * float4)
#define TILE_Y 8            // output rows per block
#define SMEM_W 140          // (TILE_X + 10) padded to multiple of 4 for LDS.128
#define SMEM_H (TILE_Y + 10)
#define PLANE (H * W)       // 65536

__global__ __launch_bounds__(256)
void dynamic_filter_kernel(const float* __restrict__ image,
                           const float* __restrict__ filters,
                           float* __restrict__ out)
{
    __shared__ float s_img[SMEM_H * SMEM_W];

    const int tx = threadIdx.x;          // 0..31
    const int ty = threadIdx.y;          // 0..7
    const int x0 = blockIdx.x * TILE_X;  // tile origin (output coords)
    const int y0 = blockIdx.y * TILE_Y;
    const int b  = blockIdx.z;

    const float* img_b = image + (size_t)b * PLANE;

    // ---- cooperative tile fill (zero halo padding = 'same') ----
    const int tid = ty * 32 + tx;
    const int fill_cols = TILE_X + 2 * HALO;   // 138
    for (int i = tid; i < SMEM_H * fill_cols; i += 256) {
        int r = i / fill_cols;
        int c = i - r * fill_cols;
        int gy = y0 + r - HALO;
        int gx = x0 + c - HALO;
        float v = 0.0f;
        if (gy >= 0 && gy < H && gx >= 0 && gx < W)
            v = __ldg(img_b + gy * W + gx);
        s_img[r * SMEM_W + c] = v;
    }
    __syncthreads();

    // ---- main accumulation: stream 121 filter planes ----
    const int x = x0 + tx * 4;           // first of 4 outputs this thread owns
    const int y = y0 + ty;

    // filters[b, t, y, x] as float4; stride between taps = PLANE/4 float4s
    const float4* fbase =
        (const float4*)(filters + (size_t)b * TAPS * PLANE + (size_t)y * W + x);

    // Two accumulator chains (even/odd kx) to halve FFMA dependency depth.
    float4 acc0 = make_float4(0.f, 0.f, 0.f, 0.f);
    float4 acc1 = make_float4(0.f, 0.f, 0.f, 0.f);

    #pragma unroll
    for (int ky = 0; ky < KH; ky++) {
        // 16 consecutive image floats covering kx+j, kx in [0,10], j in [0,3]
        float r[16];
        const float4* srow = (const float4*)&s_img[(ty + ky) * SMEM_W + tx * 4];
        ((float4*)r)[0] = srow[0];
        ((float4*)r)[1] = srow[1];
        ((float4*)r)[2] = srow[2];
        ((float4*)r)[3] = srow[3];

        #pragma unroll
        for (int kx = 0; kx < KW; kx++) {
            // streaming (evict-first) load: filters have zero reuse
            float4 f = __ldcs(&fbase[(ky * KW + kx) * (PLANE / 4)]);
            if (kx & 1) {
                acc1.x = fmaf(f.x, r[kx + 0], acc1.x);
                acc1.y = fmaf(f.y, r[kx + 1], acc1.y);
                acc1.z = fmaf(f.z, r[kx + 2], acc1.z);
                acc1.w = fmaf(f.w, r[kx + 3], acc1.w);
            } else {
                acc0.x = fmaf(f.x, r[kx + 0], acc0.x);
                acc0.y = fmaf(f.y, r[kx + 1], acc0.y);
                acc0.z = fmaf(f.z, r[kx + 2], acc0.z);
                acc0.w = fmaf(f.w, r[kx + 3], acc0.w);
            }
        }
    }

    float4 res;
    res.x = acc0.x + acc1.x;
    res.y = acc0.y + acc1.y;
    res.z = acc0.z + acc1.z;
    res.w = acc0.w + acc1.w;
    *(float4*)(out + (size_t)b * PLANE + (size_t)y * W + x) = res;
}

extern "C" void kernel_launch(void* const* d_in, const int* in_sizes, int n_in,
                              void* d_out, int out_size)
{
    const float* image   = (const float*)d_in[0];   // 16*1*256*256
    const float* filters = (const float*)d_in[1];   // 16*121*256*256
    float* out = (float*)d_out;                     // 16*1*256*256

    dim3 block(32, 8, 1);
    dim3 grid(W / TILE_X, H / TILE_Y, 16);          // (2, 32, 16) = 1024 blocks
    dynamic_filter_kernel<<<grid, block>>>(image, filters, out);
}

// round 8
// speedup vs baseline: 1.0251x; 1.0251x over previous
#include <cuda_runtime.h>

// DynamicFilterLayer: out[b,0,y,x] = sum_{ky,kx in 11x11} image[b,0,y+ky-5,x+kx-5] * filters[b,ky*11+kx,y,x]
// image:   (16, 1, 256, 256)  float32  (4 MB, reused 121x -> shared tile)
// filters: (16, 121, 256, 256) float32 (507 MB, read once -> __ldcs stream)
// out:     (16, 1, 256, 256)  float32
//
// Pure HBM-stream kernel. R3 measured (1024-block version): 82.4us @ 6.04 TB/s,
// DRAM 76.2% -- block-granular wave quantization: ~740 blocks in [0,T], 284 in
// [T,2T] at 38% chip width => avg ~76%. This version: 512 blocks x 2 tiles.
// 512 < 740 resident slots (43 regs -> 5 blocks/SM x 148) => ALL blocks
// concurrent from t=0, no waves, DRAM-throttled self-balancing stream.

#define H 256
#define W 256
#define KH 11
#define KW 11
#define HALO 5
#define TAPS 121
#define TILE_X 128          // output pixels in x per tile (32 threads * float4)
#define TILE_Y 8            // output rows per tile
#define SMEM_W 140          // (TILE_X + 10) padded to multiple of 4 for LDS.128
#define SMEM_H (TILE_Y + 10)
#define PLANE (H * W)       // 65536

#define TILES_X (W / TILE_X)                 // 2
#define TILES_Y (H / TILE_Y)                 // 32
#define TILES_PER_BATCH (TILES_X * TILES_Y)  // 64
#define TOTAL_TILES (TILES_PER_BATCH * 16)   // 1024
#define GRID_BLOCKS (TOTAL_TILES / 2)        // 512, each block does 2 tiles

__global__ __launch_bounds__(256)
void dynamic_filter_kernel(const float* __restrict__ image,
                           const float* __restrict__ filters,
                           float* __restrict__ out)
{
    __shared__ float s_img[SMEM_H * SMEM_W];

    const int tx = threadIdx.x;          // 0..31
    const int ty = threadIdx.y;          // 0..7
    const int tid = ty * 32 + tx;

    #pragma unroll
    for (int iter = 0; iter < 2; iter++) {
        const int id = blockIdx.x + iter * GRID_BLOCKS;   // flattened tile id
        const int b   = id / TILES_PER_BATCH;
        const int rem = id - b * TILES_PER_BATCH;
        const int by  = rem / TILES_X;
        const int bx  = rem - by * TILES_X;
        const int x0 = bx * TILE_X;
        const int y0 = by * TILE_Y;

        const float* img_b = image + (size_t)b * PLANE;

        // ---- cooperative tile fill (zero halo padding = 'same') ----
        const int fill_cols = TILE_X + 2 * HALO;   // 138
        for (int i = tid; i < SMEM_H * fill_cols; i += 256) {
            int r = i / fill_cols;
            int c = i - r * fill_cols;
            int gy = y0 + r - HALO;
            int gx = x0 + c - HALO;
            float v = 0.0f;
            if (gy >= 0 && gy < H && gx >= 0 && gx < W)
                v = __ldg(img_b + gy * W + gx);
            s_img[r * SMEM_W + c] = v;
        }
        __syncthreads();

        // ---- main accumulation: stream 121 filter planes ----
        const int x = x0 + tx * 4;       // first of 4 outputs this thread owns
        const int y = y0 + ty;

        const float4* fbase =
            (const float4*)(filters + (size_t)b * TAPS * PLANE + (size_t)y * W + x);

        // Two accumulator chains (even/odd kx) to halve FFMA dependency depth.
        float4 acc0 = make_float4(0.f, 0.f, 0.f, 0.f);
        float4 acc1 = make_float4(0.f, 0.f, 0.f, 0.f);

        #pragma unroll
        for (int ky = 0; ky < KH; ky++) {
            // 16 consecutive image floats covering kx+j, kx in [0,10], j in [0,3]
            float r[16];
            const float4* srow = (const float4*)&s_img[(ty + ky) * SMEM_W + tx * 4];
            ((float4*)r)[0] = srow[0];
            ((float4*)r)[1] = srow[1];
            ((float4*)r)[2] = srow[2];
            ((float4*)r)[3] = srow[3];

            #pragma unroll
            for (int kx = 0; kx < KW; kx++) {
                // streaming (evict-first) load: filters have zero reuse
                float4 f = __ldcs(&fbase[(ky * KW + kx) * (PLANE / 4)]);
                if (kx & 1) {
                    acc1.x = fmaf(f.x, r[kx + 0], acc1.x);
                    acc1.y = fmaf(f.y, r[kx + 1], acc1.y);
                    acc1.z = fmaf(f.z, r[kx + 2], acc1.z);
                    acc1.w = fmaf(f.w, r[kx + 3], acc1.w);
                } else {
                    acc0.x = fmaf(f.x, r[kx + 0], acc0.x);
                    acc0.y = fmaf(f.y, r[kx + 1], acc0.y);
                    acc0.z = fmaf(f.z, r[kx + 2], acc0.z);
                    acc0.w = fmaf(f.w, r[kx + 3], acc0.w);
                }
            }
        }

        float4 res;
        res.x = acc0.x + acc1.x;
        res.y = acc0.y + acc1.y;
        res.z = acc0.z + acc1.z;
        res.w = acc0.w + acc1.w;
        *(float4*)(out + (size_t)b * PLANE + (size_t)y * W + x) = res;

        // protect s_img from next iteration's refill
        __syncthreads();
    }
}

extern "C" void kernel_launch(void* const* d_in, const int* in_sizes, int n_in,
                              void* d_out, int out_size)
{
    const float* image   = (const float*)d_in[0];   // 16*1*256*256
    const float* filters = (const float*)d_in[1];   // 16*121*256*256
    float* out = (float*)d_out;                     // 16*1*256*256

    dim3 block(32, 8, 1);
    dim3 grid(GRID_BLOCKS, 1, 1);        // 512 blocks, single concurrent wave
    dynamic_filter_kernel<<<grid, block>>>(image, filters, out);
}

// round 14
// speedup vs baseline: 1.0316x; 1.0064x over previous
#include <cuda_runtime.h>
#include <cstdint>

// DynamicFilterLayer: out[b,0,y,x] = sum_{ky,kx in 11x11} image[b,0,y+ky-5,x+kx-5] * filters[b,ky*11+kx,y,x]
// image:   (16, 1, 256, 256)  float32  (4 MB, reused 121x -> shared tile)
// filters: (16, 121, 256, 256) float32 (507 MB, read once -> __ldcs stream)
// out:     (16, 1, 256, 256)  float32
//
// R8 measured (512 blocks x 2 tiles): 80.4us @ 6.36 TB/s, DRAM 80.3%, occ 42%.
// Remaining gap = serial image-fill bubbles at tile boundaries. This design
// (resubmitted; broker timeouts have kept it off hardware): double-buffered
// image tile with cp.async prefetch -- both tiles' fills issued before
// compute; tile 2's fill completes under tile 1's ~40us filter stream, so the
// mid boundary becomes wait_group(0)+bar on long-landed data.

#define H 256
#define W 256
#define KH 11
#define KW 11
#define HALO 5
#define TAPS 121
#define TILE_X 128          // output pixels in x per tile (32 threads * float4)
#define TILE_Y 8            // output rows per tile
#define SMEM_W 140          // (TILE_X + 10) padded to multiple of 4 for LDS.128
#define SMEM_H (TILE_Y + 10)
#define FILL_COLS (TILE_X + 2 * HALO)   // 138
#define PLANE (H * W)       // 65536

#define TILES_X (W / TILE_X)                 // 2
#define TILES_Y (H / TILE_Y)                 // 32
#define TILES_PER_BATCH (TILES_X * TILES_Y)  // 64
#define TOTAL_TILES (TILES_PER_BATCH * 16)   // 1024
#define GRID_BLOCKS (TOTAL_TILES / 2)        // 512, each block does 2 tiles

__device__ __forceinline__ void cp_async4(uint32_t dst_smem, const float* src, int src_size)
{
    // 4-byte async copy with zero-fill when src_size == 0 (halo padding)
    asm volatile("cp.async.ca.shared.global [%0], [%1], 4, %2;\n"
                 :: "r"(dst_smem), "l"(src), "r"(src_size));
}

__global__ __launch_bounds__(256)
void dynamic_filter_kernel(const float* __restrict__ image,
                           const float* __restrict__ filters,
                           float* __restrict__ out)
{
    __shared__ __align__(16) float s_img[2][SMEM_H * SMEM_W];

    const int tx = threadIdx.x;          // 0..31
    const int ty = threadIdx.y;          // 0..7
    const int tid = ty * 32 + tx;

    // tile descriptors for both iterations
    int tb[2], tx0[2], ty0[2];
    #pragma unroll
    for (int it = 0; it < 2; it++) {
        const int id  = blockIdx.x + it * GRID_BLOCKS;
        const int b   = id / TILES_PER_BATCH;
        const int rem = id - b * TILES_PER_BATCH;
        const int by  = rem / TILES_X;
        const int bx  = rem - by * TILES_X;
        tb[it]  = b;
        tx0[it] = bx * TILE_X;
        ty0[it] = by * TILE_Y;
    }

    // ---- issue async fills for BOTH tiles up front ----
    #pragma unroll
    for (int it = 0; it < 2; it++) {
        const float* img_b = image + (size_t)tb[it] * PLANE;
        const int x0 = tx0[it], y0 = ty0[it];
        for (int i = tid; i < SMEM_H * FILL_COLS; i += 256) {
            int r = i / FILL_COLS;
            int c = i - r * FILL_COLS;
            int gy = y0 + r - HALO;
            int gx = x0 + c - HALO;
            bool in = (gy >= 0 && gy < H && gx >= 0 && gx < W);
            const float* src = img_b + (in ? (gy * W + gx) : 0);  // clamped addr
            uint32_t dst = (uint32_t)__cvta_generic_to_shared(
                               &s_img[it][r * SMEM_W + c]);
            cp_async4(dst, src, in ? 4 : 0);
        }
        asm volatile("cp.async.commit_group;\n" ::: "memory");
    }

    // wait for tile-0 fill only (group 1 may still be in flight)
    asm volatile("cp.async.wait_group 1;\n" ::: "memory");
    __syncthreads();

    #pragma unroll
    for (int iter = 0; iter < 2; iter++) {
        const int x = tx0[iter] + tx * 4;    // first of 4 outputs this thread owns
        const int y = ty0[iter] + ty;

        const float4* fbase =
            (const float4*)(filters + (size_t)tb[iter] * TAPS * PLANE
                            + (size_t)y * W + x);

        // Two accumulator chains (even/odd kx) to halve FFMA dependency depth.
        float4 acc0 = make_float4(0.f, 0.f, 0.f, 0.f);
        float4 acc1 = make_float4(0.f, 0.f, 0.f, 0.f);

        #pragma unroll
        for (int ky = 0; ky < KH; ky++) {
            // 16 consecutive image floats covering kx+j, kx in [0,10], j in [0,3]
            float r[16];
            const float4* srow =
                (const float4*)&s_img[iter][(ty + ky) * SMEM_W + tx * 4];
            ((float4*)r)[0] = srow[0];
            ((float4*)r)[1] = srow[1];
            ((float4*)r)[2] = srow[2];
            ((float4*)r)[3] = srow[3];

            #pragma unroll
            for (int kx = 0; kx < KW; kx++) {
                // streaming (evict-first) load: filters have zero reuse
                float4 f = __ldcs(&fbase[(ky * KW + kx) * (PLANE / 4)]);
                if (kx & 1) {
                    acc1.x = fmaf(f.x, r[kx + 0], acc1.x);
                    acc1.y = fmaf(f.y, r[kx + 1], acc1.y);
                    acc1.z = fmaf(f.z, r[kx + 2], acc1.z);
                    acc1.w = fmaf(f.w, r[kx + 3], acc1.w);
                } else {
                    acc0.x = fmaf(f.x, r[kx + 0], acc0.x);
                    acc0.y = fmaf(f.y, r[kx + 1], acc0.y);
                    acc0.z = fmaf(f.z, r[kx + 2], acc0.z);
                    acc0.w = fmaf(f.w, r[kx + 3], acc0.w);
                }
            }
        }

        float4 res;
        res.x = acc0.x + acc1.x;
        res.y = acc0.y + acc1.y;
        res.z = acc0.z + acc1.z;
        res.w = acc0.w + acc1.w;
        *(float4*)(out + (size_t)tb[iter] * PLANE + (size_t)y * W + x) = res;

        if (iter == 0) {
            // tile-1 image landed long ago under the filter stream; just drain
            asm volatile("cp.async.wait_group 0;\n" ::: "memory");
            __syncthreads();
        }
    }
}

extern "C" void kernel_launch(void* const* d_in, const int* in_sizes, int n_in,
                              void* d_out, int out_size)
{
    const float* image   = (const float*)d_in[0];   // 16*1*256*256
    const float* filters = (const float*)d_in[1];   // 16*121*256*256
    float* out = (float*)d_out;                     // 16*1*256*256

    dim3 block(32, 8, 1);
    dim3 grid(GRID_BLOCKS, 1, 1);        // 512 blocks, single concurrent wave
    dynamic_filter_kernel<<<grid, block>>>(image, filters, out);
}